// round 1
// baseline (speedup 1.0000x reference)
#include <cuda_runtime.h>
#include <cuda_fp16.h>
#include <mma.h>

using namespace nvcuda;

#define DIMD 512
#define NBATCH 4096
#define NSLOTS 64
#define M_TOTAL (NBATCH * NSLOTS)   /* 262144 rows */
#define NCLS 4
#define KTOP 16
#define NBLK 8                      /* 512 / 64 n-blocks */

// ---------------- scratch (static device memory; no allocations) ----------------
__device__ __half g_w1h[DIMD * DIMD], g_w1l[DIMD * DIMD];
__device__ __half g_w2h[DIMD * DIMD], g_w2l[DIMD * DIMD];
__device__ __half g_wkh[DIMD * DIMD], g_wkl[DIMD * DIMD];
__device__ __half g_h_hi[(size_t)M_TOTAL * DIMD], g_h_lo[(size_t)M_TOTAL * DIMD];
__device__ __half g_s_hi[(size_t)M_TOTAL * DIMD], g_s_lo[(size_t)M_TOTAL * DIMD];
__device__ float  g_logits_part[(size_t)NBLK * M_TOTAL * NCLS];
__device__ float  g_keep_part[(size_t)NBLK * M_TOTAL];

// ---------------- weight split: fp32 -> (hi, lo) fp16 pair ----------------
__global__ void prep_kernel(const float* __restrict__ W1,
                            const float* __restrict__ W2,
                            const float* __restrict__ Wk1) {
    int i = blockIdx.x * blockDim.x + threadIdx.x;
    if (i >= DIMD * DIMD) return;
    float x;
    __half h;
    x = W1[i];  h = __float2half_rn(x); g_w1h[i] = h; g_w1l[i] = __float2half_rn(x - __half2float(h));
    x = W2[i];  h = __float2half_rn(x); g_w2h[i] = h; g_w2l[i] = __float2half_rn(x - __half2float(h));
    x = Wk1[i]; h = __float2half_rn(x); g_wkh[i] = h; g_wkl[i] = __float2half_rn(x - __half2float(h));
}

// ---------------- fused GEMM: C[m,n] = sum_k A[m,k] * W[n,k] (+bias, epilogue per MODE)
// MODE 1: A = slots (f32, converted on the fly), out = relu -> g_h (hi/lo)
// MODE 2: A = g_h,  out = g_s (hi/lo) + fused slot_logits partials (s . Wd^T)
// MODE 3: A = g_s,  out = fused keep_score partials (relu(.) . Wk2), nothing stored
// Split fp16 accuracy: acc += Ah*Bh + Ah*Bl + Al*Bh  (error ~ eps_fp16^2)
template <int MODE>
__global__ __launch_bounds__(256, 2)
void gemm_kernel(const float* __restrict__ A32,
                 const float* __restrict__ bias,
                 const float* __restrict__ Wd,
                 const float* __restrict__ Wk2) {
    __shared__ __align__(16) unsigned char smem_buf[36352];
    __half* Ash = (__half*)smem_buf;            // [128][40]
    __half* Asl = Ash + 128 * 40;               // offset 10240 B
    __half* Bsh = Asl + 128 * 40;               // offset 20480 B, [64][40]
    __half* Bsl = Bsh + 64 * 40;                // offset 25600 B
    float*  Cs  = (float*)smem_buf;             // [128][68] overlays staging (after sync)
    float*  bias_s = (float*)(smem_buf + 34816);
    float*  wd_s   = (float*)(smem_buf + 35072);   // [4][64]
    float*  wk_s   = (float*)(smem_buf + 36096);   // [64]

    const __half* Ahi = nullptr; const __half* Alo = nullptr;
    const __half* Bhi = nullptr; const __half* Blo = nullptr;
    __half* Ohi = nullptr; __half* Olo = nullptr;
    if (MODE == 1) { Bhi = g_w1h; Blo = g_w1l; Ohi = g_h_hi; Olo = g_h_lo; }
    if (MODE == 2) { Ahi = g_h_hi; Alo = g_h_lo; Bhi = g_w2h; Blo = g_w2l; Ohi = g_s_hi; Olo = g_s_lo; }
    if (MODE == 3) { Ahi = g_s_hi; Alo = g_s_lo; Bhi = g_wkh; Blo = g_wkl; }

    const int tid = threadIdx.x;
    const int n0 = blockIdx.x * 64;
    const int m0 = blockIdx.y * 128;

    if (tid < 64) bias_s[tid] = bias[n0 + tid];
    if (MODE == 2) { int cc = tid >> 6, j = tid & 63; wd_s[cc * 64 + j] = Wd[cc * DIMD + n0 + j]; }
    if (MODE == 3 && tid < 64) wk_s[tid] = Wk2[n0 + tid];

    const int warp = tid >> 5;
    const int wm = warp & 3, wn = warp >> 2;   // 4 x 2 warp grid; warp tile 32x32

    wmma::fragment<wmma::accumulator, 16, 16, 16, float> acc[2][2];
#pragma unroll
    for (int i = 0; i < 2; i++)
#pragma unroll
        for (int j = 0; j < 2; j++) wmma::fill_fragment(acc[i][j], 0.0f);

    for (int kt = 0; kt < DIMD; kt += 32) {
        if (MODE == 1) {
#pragma unroll
            for (int it = 0; it < 4; it++) {
                int v = tid + it * 256;              // 0..1023 -> 128 rows x 8 float4
                int r = v >> 3, c4 = (v & 7) * 4;
                float4 f = *(const float4*)(A32 + (size_t)(m0 + r) * DIMD + kt + c4);
                __half h0 = __float2half_rn(f.x), h1 = __float2half_rn(f.y);
                __half h2 = __float2half_rn(f.z), h3 = __float2half_rn(f.w);
                __half l0 = __float2half_rn(f.x - __half2float(h0));
                __half l1 = __float2half_rn(f.y - __half2float(h1));
                __half l2 = __float2half_rn(f.z - __half2float(h2));
                __half l3 = __float2half_rn(f.w - __half2float(h3));
                *(__half2*)(Ash + r * 40 + c4)     = __halves2half2(h0, h1);
                *(__half2*)(Ash + r * 40 + c4 + 2) = __halves2half2(h2, h3);
                *(__half2*)(Asl + r * 40 + c4)     = __halves2half2(l0, l1);
                *(__half2*)(Asl + r * 40 + c4 + 2) = __halves2half2(l2, l3);
            }
        } else {
#pragma unroll
            for (int it = 0; it < 2; it++) {
                int v = tid + it * 256;              // 0..511 -> 128 rows x 4 uint4
                int r = v >> 2, c8 = (v & 3) * 8;
                *(uint4*)(Ash + r * 40 + c8) = *(const uint4*)(Ahi + (size_t)(m0 + r) * DIMD + kt + c8);
                *(uint4*)(Asl + r * 40 + c8) = *(const uint4*)(Alo + (size_t)(m0 + r) * DIMD + kt + c8);
            }
        }
        {
            int r = tid >> 2, c8 = (tid & 3) * 8;    // 64 rows x 4 uint4
            *(uint4*)(Bsh + r * 40 + c8) = *(const uint4*)(Bhi + (size_t)(n0 + r) * DIMD + kt + c8);
            *(uint4*)(Bsl + r * 40 + c8) = *(const uint4*)(Blo + (size_t)(n0 + r) * DIMD + kt + c8);
        }
        __syncthreads();

#pragma unroll
        for (int ks = 0; ks < 32; ks += 16) {
            wmma::fragment<wmma::matrix_a, 16, 16, 16, __half, wmma::row_major> ah[2], al[2];
#pragma unroll
            for (int i = 0; i < 2; i++) {
                wmma::load_matrix_sync(ah[i], Ash + (wm * 32 + i * 16) * 40 + ks, 40);
                wmma::load_matrix_sync(al[i], Asl + (wm * 32 + i * 16) * 40 + ks, 40);
            }
#pragma unroll
            for (int j = 0; j < 2; j++) {
                wmma::fragment<wmma::matrix_b, 16, 16, 16, __half, wmma::col_major> bh, bl;
                wmma::load_matrix_sync(bh, Bsh + (wn * 32 + j * 16) * 40 + ks, 40);
                wmma::load_matrix_sync(bl, Bsl + (wn * 32 + j * 16) * 40 + ks, 40);
#pragma unroll
                for (int i = 0; i < 2; i++) {
                    wmma::mma_sync(acc[i][j], ah[i], bh, acc[i][j]);
                    wmma::mma_sync(acc[i][j], ah[i], bl, acc[i][j]);
                    wmma::mma_sync(acc[i][j], al[i], bh, acc[i][j]);
                }
            }
        }
        __syncthreads();
    }

    // ---- epilogue ----
#pragma unroll
    for (int i = 0; i < 2; i++)
#pragma unroll
        for (int j = 0; j < 2; j++)
            wmma::store_matrix_sync(Cs + (wm * 32 + i * 16) * 68 + (wn * 32 + j * 16),
                                    acc[i][j], 68, wmma::mem_row_major);
    __syncthreads();

    const int r = tid >> 1;
    const int ch = (tid & 1) * 32;
    const size_t row_g = (size_t)m0 + r;
    float lg0 = 0.f, lg1 = 0.f, lg2 = 0.f, lg3 = 0.f, kp = 0.f;
#pragma unroll
    for (int c = 0; c < 32; c += 2) {
        int col = ch + c;
        float v0 = Cs[r * 68 + col]     + bias_s[col];
        float v1 = Cs[r * 68 + col + 1] + bias_s[col + 1];
        if (MODE == 1) { v0 = fmaxf(v0, 0.f); v1 = fmaxf(v1, 0.f); }
        if (MODE <= 2) {
            __half h0 = __float2half_rn(v0), h1 = __float2half_rn(v1);
            __half l0 = __float2half_rn(v0 - __half2float(h0));
            __half l1 = __float2half_rn(v1 - __half2float(h1));
            *(__half2*)(Ohi + row_g * DIMD + n0 + col) = __halves2half2(h0, h1);
            *(__half2*)(Olo + row_g * DIMD + n0 + col) = __halves2half2(l0, l1);
        }
        if (MODE == 2) {
            lg0 += v0 * wd_s[0 * 64 + col] + v1 * wd_s[0 * 64 + col + 1];
            lg1 += v0 * wd_s[1 * 64 + col] + v1 * wd_s[1 * 64 + col + 1];
            lg2 += v0 * wd_s[2 * 64 + col] + v1 * wd_s[2 * 64 + col + 1];
            lg3 += v0 * wd_s[3 * 64 + col] + v1 * wd_s[3 * 64 + col + 1];
        }
        if (MODE == 3) {
            kp += fmaxf(v0, 0.f) * wk_s[col] + fmaxf(v1, 0.f) * wk_s[col + 1];
        }
    }
    if (MODE == 2) {
        lg0 += __shfl_xor_sync(0xffffffffu, lg0, 1);
        lg1 += __shfl_xor_sync(0xffffffffu, lg1, 1);
        lg2 += __shfl_xor_sync(0xffffffffu, lg2, 1);
        lg3 += __shfl_xor_sync(0xffffffffu, lg3, 1);
        if ((tid & 1) == 0) {
            float4 o = make_float4(lg0, lg1, lg2, lg3);
            *(float4*)(g_logits_part + ((size_t)blockIdx.x * M_TOTAL + row_g) * 4) = o;
        }
    }
    if (MODE == 3) {
        kp += __shfl_xor_sync(0xffffffffu, kp, 1);
        if ((tid & 1) == 0)
            g_keep_part[(size_t)blockIdx.x * M_TOTAL + row_g] = kp;
    }
}

// ---------------- per-batch top-k / softmax / gating / output ----------------
__global__ void final_kernel(const float* __restrict__ bd,
                             const float* __restrict__ bk2,
                             float* __restrict__ out) {
    __shared__ float sc[NSLOTS];
    __shared__ float ex[NSLOTS];
    __shared__ float gt[NSLOTS];
    __shared__ float red[NSLOTS * NCLS];
    const int b = blockIdx.x;
    const int s = threadIdx.x;           // 64 threads, one per slot
    const size_t m = (size_t)b * NSLOTS + s;

    float score = bk2[0];
#pragma unroll
    for (int nb = 0; nb < NBLK; nb++) score += g_keep_part[(size_t)nb * M_TOTAL + m];
    sc[s] = score;
    __syncthreads();

    float mx = -1e30f; int cnt = 0;
#pragma unroll 8
    for (int j = 0; j < NSLOTS; j++) {
        float v = sc[j];
        mx = fmaxf(mx, v);
        cnt += (v > score) || (v == score && j < s);
    }
    float e = expf((score - mx) * 100.0f);  // temperature 0.01
    ex[s] = e;
    __syncthreads();
    float sum = 0.f;
#pragma unroll 8
    for (int j = 0; j < NSLOTS; j++) sum += ex[j];
    float soft = e / sum;
    float hardf = (cnt < KTOP) ? 1.0f : 0.0f;
    float hard_keep = (hardf + soft) - soft;   // matches JAX ST-estimator fp order
    float gate = soft * hard_keep;
    gt[s] = gate;
    __syncthreads();
    float gsum = 0.f;
#pragma unroll 8
    for (int j = 0; j < NSLOTS; j++) gsum += gt[j];
    gate = gate / (gsum + 1e-8f);

    out[(size_t)NBATCH * NCLS + m] = gate;                          // slot_gate
    out[(size_t)NBATCH * NCLS + (size_t)NBATCH * NSLOTS + m] = hard_keep;  // hard_keep

#pragma unroll
    for (int c = 0; c < NCLS; c++) {
        float v = bd[c];
#pragma unroll
        for (int nb = 0; nb < NBLK; nb++)
            v += g_logits_part[((size_t)nb * M_TOTAL + m) * 4 + c];
        red[s * NCLS + c] = gate * v;
    }
    __syncthreads();
    if (s < NCLS) {
        float acc = 0.f;
#pragma unroll 8
        for (int j = 0; j < NSLOTS; j++) acc += red[j * NCLS + s];
        out[(size_t)b * NCLS + s] = acc;   // x
    }
}

extern "C" void kernel_launch(void* const* d_in, const int* in_sizes, int n_in,
                              void* d_out, int out_size) {
    const float* slots = (const float*)d_in[0];
    const float* W1    = (const float*)d_in[1];
    const float* b1    = (const float*)d_in[2];
    const float* W2    = (const float*)d_in[3];
    const float* b2    = (const float*)d_in[4];
    const float* Wd    = (const float*)d_in[5];
    const float* bd    = (const float*)d_in[6];
    const float* Wk1   = (const float*)d_in[7];
    const float* bk1   = (const float*)d_in[8];
    const float* Wk2   = (const float*)d_in[9];
    const float* bk2   = (const float*)d_in[10];
    float* out = (float*)d_out;

    prep_kernel<<<(DIMD * DIMD + 255) / 256, 256>>>(W1, W2, Wk1);
    dim3 grid(NBLK, M_TOTAL / 128);
    gemm_kernel<1><<<grid, 256>>>(slots, b1, nullptr, nullptr);
    gemm_kernel<2><<<grid, 256>>>(nullptr, b2, Wd, nullptr);
    gemm_kernel<3><<<grid, 256>>>(nullptr, bk1, nullptr, Wk2);
    final_kernel<<<NBATCH, NSLOTS>>>(bd, bk2, out);
}